// round 8
// baseline (speedup 1.0000x reference)
#include <cuda_runtime.h>
#include <cuda_fp16.h>
#include <cstdint>
#include <type_traits>

#define NN 50000
#define DD 128
#define K2 256
#define EE 800000
#define EPS 1e-5f

// ---------------- scratch (device globals) ----------------------------------
__device__ float  g_agg[NN * DD];        // per-block gathered rows (staging)
__device__ __half g_h0[NN * DD];
__device__ __half g_h1[NN * DD];
__device__ float  g_Wt3[3 * K2 * DD];
__device__ float  g_stats3[3][2 * DD];   // per-layer [sum | sumsq]
__device__ int    g_deg[NN];
__device__ int    g_rowptr[NN + 1];
__device__ int    g_cursor[NN];
__device__ int    g_col[EE];
__device__ int    g_bsum[64];
__device__ int    g_scan_count;

// ---------------- CSR build --------------------------------------------------
__global__ void count_kernel(const int* __restrict__ ei, int E) {
    int e = blockIdx.x * blockDim.x + threadIdx.x;
    if (e < E) {
        int d = ei[E + e];
        if (d >= 0 && d < NN) atomicAdd(&g_deg[d], 1);
    }
}

__global__ void scan_fused_kernel() {
    __shared__ int wsum[32];
    __shared__ int s_off;
    int t = threadIdx.x, b = blockIdx.x;
    int idx = b * 1024 + t;
    int wid = t >> 5, lane = t & 31;
    int v = (idx < NN) ? g_deg[idx] : 0;
    int incl = v;
#pragma unroll
    for (int off = 1; off < 32; off <<= 1) {
        int y = __shfl_up_sync(0xffffffffu, incl, off);
        if (lane >= off) incl += y;
    }
    if (lane == 31) wsum[wid] = incl;
    __syncthreads();
    if (wid == 0) {
        int si = wsum[lane];
#pragma unroll
        for (int off = 1; off < 32; off <<= 1) {
            int y = __shfl_up_sync(0xffffffffu, si, off);
            if (lane >= off) si += y;
        }
        wsum[lane] = si;
    }
    __syncthreads();
    int total = wsum[31];
    if (t == 0) {
        g_bsum[b] = total;
        __threadfence();
        atomicAdd(&g_scan_count, 1);
        while (atomicAdd(&g_scan_count, 0) < (int)gridDim.x) {}
        __threadfence();
        int off = 0;
        for (int j = 0; j < b; j++) off += g_bsum[j];
        s_off = off;
    }
    __syncthreads();
    int woff = (wid > 0) ? wsum[wid - 1] : 0;
    if (idx < NN) {
        int r = s_off + woff + incl - v;
        g_rowptr[idx] = r;
        g_cursor[idx] = r;
    }
    if (b == gridDim.x - 1 && t == 0) g_rowptr[NN] = s_off + total;
}

__global__ void fill_kernel(const int* __restrict__ ei, int E) {
    int e = blockIdx.x * blockDim.x + threadIdx.x;
    if (e < E) {
        int s = ei[e];
        int d = ei[E + e];
        if (d >= 0 && d < NN) {
            int pos = atomicAdd(&g_cursor[d], 1);
            g_col[pos] = s;
        }
    }
}

// ---------------- weight prep + zero deg + zero stats + scan reset ----------
__global__ void prep_w_all(const float* __restrict__ Wl0, const float* __restrict__ Wr0,
                           const float* __restrict__ Wl1, const float* __restrict__ Wr1,
                           const float* __restrict__ Wl2, const float* __restrict__ Wr2) {
    int i = blockIdx.x * blockDim.x + threadIdx.x;
    if (i == 0) g_scan_count = 0;
    if (i < NN / 4) ((int4*)g_deg)[i] = make_int4(0, 0, 0, 0);
    if (i < 6 * DD) ((float*)g_stats3)[i] = 0.f;
    if (i >= 3 * K2 * DD) return;
    int L = i / (K2 * DD);
    int r = i - L * (K2 * DD);
    int k = r >> 7, j = r & 127;
    const float* Wl = (L == 0) ? Wl0 : (L == 1 ? Wl1 : Wl2);
    const float* Wr = (L == 0) ? Wr0 : (L == 1 ? Wr1 : Wr2);
    g_Wt3[i] = (k < DD) ? __ldg(&Wl[j * DD + k]) : __ldg(&Wr[j * DD + (k - DD)]);
}

// ---------------- fused layer: gather + 3xTF32 GEMM + BN stats ---------------
#define ASTRIDE 20
#define BSTRIDE 136

__device__ __forceinline__ void split_tf32(float v, uint32_t& hi, uint32_t& lo) {
    asm("cvt.rna.tf32.f32 %0, %1;" : "=r"(hi) : "f"(v));
    float l = v - __uint_as_float(hi);
    asm("cvt.rna.tf32.f32 %0, %1;" : "=r"(lo) : "f"(l));
}

__device__ __forceinline__ void mma_tf32(float* d, uint32_t a0, uint32_t a1,
                                         uint32_t a2, uint32_t a3,
                                         uint32_t b0, uint32_t b1) {
    asm volatile(
        "mma.sync.aligned.m16n8k8.row.col.f32.tf32.tf32.f32 "
        "{%0,%1,%2,%3},{%4,%5,%6,%7},{%8,%9},{%0,%1,%2,%3};"
        : "+f"(d[0]), "+f"(d[1]), "+f"(d[2]), "+f"(d[3])
        : "r"(a0), "r"(a1), "r"(a2), "r"(a3), "r"(b0), "r"(b1));
}

// TI: input feature type; XFORM: apply BN(prev)+ReLU to inputs; TO: output type
template <typename TI, int XFORM, typename TO>
__global__ __launch_bounds__(128, 2)
void layer_kernel(const TI* __restrict__ Xin,
                  const float* __restrict__ Wt,
                  const float* __restrict__ bias,
                  const float* __restrict__ prev_stats,
                  const float* __restrict__ prev_gamma,
                  const float* __restrict__ prev_beta,
                  float* __restrict__ cur_stats,
                  TO* __restrict__ Y) {
    __shared__ float As_hi[128 * ASTRIDE];
    __shared__ float As_lo[128 * ASTRIDE];
    __shared__ float Bs_hi[16 * BSTRIDE];
    __shared__ float Bs_lo[16 * BSTRIDE];
    __shared__ float bias_s[128];
    __shared__ float sc_s[128];
    __shared__ float sh_s[128];

    int tid = threadIdx.x;
    int brow = blockIdx.x * 128;
    int wid = tid >> 5, lane = tid & 31;
    int group = lane >> 2, tg = lane & 3;
    int warp_m = (wid >> 1) * 64, warp_n = (wid & 1) * 64;

    // compute BN affine of previous layer from raw sums (cheap, per block)
    if (tid < 128) {
        bias_s[tid] = __ldg(&bias[tid]);
        if (XFORM) {
            float m = __ldg(&prev_stats[tid]) * (1.0f / NN);
            float var = __ldg(&prev_stats[DD + tid]) * (1.0f / NN) - m * m;
            float sc = __ldg(&prev_gamma[tid]) * rsqrtf(var + EPS);
            sc_s[tid] = sc;
            sh_s[tid] = __ldg(&prev_beta[tid]) - m * sc;
        }
    }
    __syncthreads();

    // ---- Phase 1: gather this block's 128 rows into g_agg ----
    {
        float4 s4, b4;
        if (XFORM) {
            s4 = ((const float4*)sc_s)[lane];
            b4 = ((const float4*)sh_s)[lane];
        }
        for (int n = 0; n < 32; n++) {
            int r = brow + wid * 32 + n;
            if (r >= NN) break;
            int start = __ldg(&g_rowptr[r]);
            int end = __ldg(&g_rowptr[r + 1]);
            float4 acc = make_float4(0.f, 0.f, 0.f, 0.f);
            int i = start;
            if constexpr (std::is_same_v<TI, __half>) {
                auto addv = [&](uint2 raw) {
                    __half2 ha = *reinterpret_cast<__half2*>(&raw.x);
                    __half2 hb = *reinterpret_cast<__half2*>(&raw.y);
                    float2 f0 = __half22float2(ha);
                    float2 f1 = __half22float2(hb);
                    acc.x += fmaxf(fmaf(f0.x, s4.x, b4.x), 0.f);
                    acc.y += fmaxf(fmaf(f0.y, s4.y, b4.y), 0.f);
                    acc.z += fmaxf(fmaf(f1.x, s4.z, b4.z), 0.f);
                    acc.w += fmaxf(fmaf(f1.y, s4.w, b4.w), 0.f);
                };
                for (; i + 7 < end; i += 8) {
                    int sidx[8];
#pragma unroll
                    for (int u = 0; u < 8; u++) sidx[u] = __ldg(&g_col[i + u]);
                    uint2 rr[8];
#pragma unroll
                    for (int u = 0; u < 8; u++)
                        rr[u] = __ldg((const uint2*)(Xin + (size_t)sidx[u] * DD) + lane);
#pragma unroll
                    for (int u = 0; u < 8; u++) addv(rr[u]);
                }
                for (; i < end; i++) {
                    int s = __ldg(&g_col[i]);
                    addv(__ldg((const uint2*)(Xin + (size_t)s * DD) + lane));
                }
            } else {
                for (; i + 7 < end; i += 8) {
                    int sidx[8];
#pragma unroll
                    for (int u = 0; u < 8; u++) sidx[u] = __ldg(&g_col[i + u]);
                    float4 vv[8];
#pragma unroll
                    for (int u = 0; u < 8; u++)
                        vv[u] = __ldg((const float4*)(Xin + (size_t)sidx[u] * DD) + lane);
#pragma unroll
                    for (int u = 0; u < 8; u++) {
                        acc.x += vv[u].x; acc.y += vv[u].y;
                        acc.z += vv[u].z; acc.w += vv[u].w;
                    }
                }
                for (; i < end; i++) {
                    int s = __ldg(&g_col[i]);
                    float4 v = __ldg((const float4*)(Xin + (size_t)s * DD) + lane);
                    acc.x += v.x; acc.y += v.y; acc.z += v.z; acc.w += v.w;
                }
            }
            float inv = 1.0f / fmaxf((float)(end - start), 1.0f);
            acc.x *= inv; acc.y *= inv; acc.z *= inv; acc.w *= inv;
            *((float4*)(g_agg + (size_t)r * DD) + lane) = acc;
        }
    }
    __syncthreads();  // agg rows of this block visible to all its threads

    // ---- Phase 2: GEMM ----
    float acc[4][8][4];
#pragma unroll
    for (int mt = 0; mt < 4; mt++)
#pragma unroll
        for (int nt = 0; nt < 8; nt++)
#pragma unroll
            for (int c = 0; c < 4; c++) acc[mt][nt][c] = 0.f;

    float4 pa[4], pb[4];

    auto load_tiles = [&](int kc) {
#pragma unroll
        for (int i = 0; i < 4; i++) {
            int l = tid + i * 128;
            int row = l >> 2, kq = l & 3;
            int r = brow + row;
            float4 v = make_float4(0.f, 0.f, 0.f, 0.f);
            if (r < NN) {
                if (kc < DD) {
                    v = *((const float4*)(g_agg + (size_t)r * DD + kc) + kq);  // own block's writes
                } else {
                    int kg = (kc - DD) + kq * 4;
                    if constexpr (std::is_same_v<TI, __half>) {
                        uint2 raw = __ldg((const uint2*)(Xin + (size_t)r * DD + kg));
                        __half2 ha = *reinterpret_cast<__half2*>(&raw.x);
                        __half2 hb = *reinterpret_cast<__half2*>(&raw.y);
                        float2 f0 = __half22float2(ha);
                        float2 f1 = __half22float2(hb);
                        v = make_float4(f0.x, f0.y, f1.x, f1.y);
                    } else {
                        v = __ldg((const float4*)(Xin + (size_t)r * DD + kg));
                    }
                    if (XFORM) {
                        float4 s4 = *(const float4*)(sc_s + kg);
                        float4 b4 = *(const float4*)(sh_s + kg);
                        v.x = fmaxf(fmaf(v.x, s4.x, b4.x), 0.f);
                        v.y = fmaxf(fmaf(v.y, s4.y, b4.y), 0.f);
                        v.z = fmaxf(fmaf(v.z, s4.z, b4.z), 0.f);
                        v.w = fmaxf(fmaf(v.w, s4.w, b4.w), 0.f);
                    }
                }
            }
            pa[i] = v;
        }
#pragma unroll
        for (int i = 0; i < 4; i++) {
            int l = tid + i * 128;
            int k = l >> 5, j4 = l & 31;
            pb[i] = __ldg((const float4*)(Wt + (size_t)(kc + k) * DD) + j4);
        }
    };

    auto store_tiles = [&]() {
#pragma unroll
        for (int i = 0; i < 4; i++) {
            int l = tid + i * 128;
            int row = l >> 2, kq = l & 3;
            float vv[4] = {pa[i].x, pa[i].y, pa[i].z, pa[i].w};
#pragma unroll
            for (int c = 0; c < 4; c++) {
                uint32_t h, lo;
                split_tf32(vv[c], h, lo);
                As_hi[row * ASTRIDE + kq * 4 + c] = __uint_as_float(h);
                As_lo[row * ASTRIDE + kq * 4 + c] = __uint_as_float(lo);
            }
        }
#pragma unroll
        for (int i = 0; i < 4; i++) {
            int l = tid + i * 128;
            int k = l >> 5, j4 = l & 31;
            float vv[4] = {pb[i].x, pb[i].y, pb[i].z, pb[i].w};
#pragma unroll
            for (int c = 0; c < 4; c++) {
                uint32_t h, lo;
                split_tf32(vv[c], h, lo);
                Bs_hi[k * BSTRIDE + j4 * 4 + c] = __uint_as_float(h);
                Bs_lo[k * BSTRIDE + j4 * 4 + c] = __uint_as_float(lo);
            }
        }
    };

    load_tiles(0);

    for (int kc = 0; kc < K2; kc += 16) {
        store_tiles();
        __syncthreads();
        if (kc + 16 < K2) load_tiles(kc + 16);

#pragma unroll
        for (int k0 = 0; k0 < 16; k0 += 8) {
            uint32_t bh0[8], bh1[8], bl0[8], bl1[8];
#pragma unroll
            for (int nt = 0; nt < 8; nt++) {
                int n = warp_n + nt * 8 + group;
                bh0[nt] = __float_as_uint(Bs_hi[(k0 + tg) * BSTRIDE + n]);
                bh1[nt] = __float_as_uint(Bs_hi[(k0 + tg + 4) * BSTRIDE + n]);
                bl0[nt] = __float_as_uint(Bs_lo[(k0 + tg) * BSTRIDE + n]);
                bl1[nt] = __float_as_uint(Bs_lo[(k0 + tg + 4) * BSTRIDE + n]);
            }
#pragma unroll
            for (int mt = 0; mt < 4; mt++) {
                int m = warp_m + mt * 16;
                uint32_t ah0 = __float_as_uint(As_hi[(m + group) * ASTRIDE + k0 + tg]);
                uint32_t ah1 = __float_as_uint(As_hi[(m + group + 8) * ASTRIDE + k0 + tg]);
                uint32_t ah2 = __float_as_uint(As_hi[(m + group) * ASTRIDE + k0 + tg + 4]);
                uint32_t ah3 = __float_as_uint(As_hi[(m + group + 8) * ASTRIDE + k0 + tg + 4]);
                uint32_t al0 = __float_as_uint(As_lo[(m + group) * ASTRIDE + k0 + tg]);
                uint32_t al1 = __float_as_uint(As_lo[(m + group + 8) * ASTRIDE + k0 + tg]);
                uint32_t al2 = __float_as_uint(As_lo[(m + group) * ASTRIDE + k0 + tg + 4]);
                uint32_t al3 = __float_as_uint(As_lo[(m + group + 8) * ASTRIDE + k0 + tg + 4]);
#pragma unroll
                for (int nt = 0; nt < 8; nt++) {
                    mma_tf32(acc[mt][nt], ah0, ah1, ah2, ah3, bh0[nt], bh1[nt]);
                    mma_tf32(acc[mt][nt], al0, al1, al2, al3, bh0[nt], bh1[nt]);
                    mma_tf32(acc[mt][nt], ah0, ah1, ah2, ah3, bl0[nt], bl1[nt]);
                }
            }
        }
        __syncthreads();
    }

    // ---- epilogue: bias + store + BN partial stats ----
    float cs[16], cq[16];
#pragma unroll
    for (int i = 0; i < 16; i++) { cs[i] = 0.f; cq[i] = 0.f; }

#pragma unroll
    for (int mt = 0; mt < 4; mt++) {
        int r0 = brow + warp_m + mt * 16 + group;
        int r1 = r0 + 8;
#pragma unroll
        for (int nt = 0; nt < 8; nt++) {
            int c = warp_n + nt * 8 + 2 * tg;
            float b0 = bias_s[c], b1 = bias_s[c + 1];
            float o0 = acc[mt][nt][0] + b0, o1 = acc[mt][nt][1] + b1;
            float o2 = acc[mt][nt][2] + b0, o3 = acc[mt][nt][3] + b1;
            if (r0 < NN) {
                if constexpr (std::is_same_v<TO, __half>) {
                    *(__half2*)(Y + (size_t)r0 * DD + c) = __floats2half2_rn(o0, o1);
                } else {
                    *(float2*)(Y + (size_t)r0 * DD + c) = make_float2(o0, o1);
                }
                cs[nt * 2 + 0] += o0; cq[nt * 2 + 0] += o0 * o0;
                cs[nt * 2 + 1] += o1; cq[nt * 2 + 1] += o1 * o1;
            }
            if (r1 < NN) {
                if constexpr (std::is_same_v<TO, __half>) {
                    *(__half2*)(Y + (size_t)r1 * DD + c) = __floats2half2_rn(o2, o3);
                } else {
                    *(float2*)(Y + (size_t)r1 * DD + c) = make_float2(o2, o3);
                }
                cs[nt * 2 + 0] += o2; cq[nt * 2 + 0] += o2 * o2;
                cs[nt * 2 + 1] += o3; cq[nt * 2 + 1] += o3 * o3;
            }
        }
    }
#pragma unroll
    for (int i = 0; i < 16; i++) {
#pragma unroll
        for (int off = 4; off < 32; off <<= 1) {
            cs[i] += __shfl_xor_sync(0xffffffffu, cs[i], off);
            cq[i] += __shfl_xor_sync(0xffffffffu, cq[i], off);
        }
    }
    if (group == 0) {
#pragma unroll
        for (int i = 0; i < 16; i++) {
            int c = warp_n + (i >> 1) * 8 + 2 * tg + (i & 1);
            atomicAdd(&cur_stats[c], cs[i]);
            atomicAdd(&cur_stats[DD + c], cq[i]);
        }
    }
}

// ---------------- final BN apply (affine computed in-block from sums) --------
__global__ void apply_kernel(float* __restrict__ Y,
                             const float* __restrict__ stats,
                             const float* __restrict__ gamma,
                             const float* __restrict__ beta) {
    __shared__ float sc_s[128];
    __shared__ float sh_s[128];
    if (threadIdx.x < 128) {
        int c = threadIdx.x;
        float m = __ldg(&stats[c]) * (1.0f / NN);
        float var = __ldg(&stats[DD + c]) * (1.0f / NN) - m * m;
        float sc = __ldg(&gamma[c]) * rsqrtf(var + EPS);
        sc_s[c] = sc;
        sh_s[c] = __ldg(&beta[c]) - m * sc;
    }
    __syncthreads();
    int i = blockIdx.x * blockDim.x + threadIdx.x;
    if (i >= NN * (DD / 4)) return;
    float4 v = ((float4*)Y)[i];
    int c = (i & (DD / 4 - 1)) * 4;
    float4 s4 = *(const float4*)(sc_s + c);
    float4 b4 = *(const float4*)(sh_s + c);
    v.x = fmaf(v.x, s4.x, b4.x);
    v.y = fmaf(v.y, s4.y, b4.y);
    v.z = fmaf(v.z, s4.z, b4.z);
    v.w = fmaf(v.w, s4.w, b4.w);
    ((float4*)Y)[i] = v;
}

// ---------------- launch ----------------------------------------------------
extern "C" void kernel_launch(void* const* d_in, const int* in_sizes, int n_in,
                              void* d_out, int out_size) {
    const float* x = (const float*)d_in[0];
    const int* ei = (const int*)d_in[1];
    const float* Wl[3] = {(const float*)d_in[2], (const float*)d_in[7], (const float*)d_in[12]};
    const float* bl[3] = {(const float*)d_in[3], (const float*)d_in[8], (const float*)d_in[13]};
    const float* Wr[3] = {(const float*)d_in[4], (const float*)d_in[9], (const float*)d_in[14]};
    const float* gm[3] = {(const float*)d_in[5], (const float*)d_in[10], (const float*)d_in[15]};
    const float* bt[3] = {(const float*)d_in[6], (const float*)d_in[11], (const float*)d_in[16]};
    int E = in_sizes[1] / 2;

    void *p_h0, *p_h1, *p_wt, *p_st;
    cudaGetSymbolAddress(&p_h0, g_h0);
    cudaGetSymbolAddress(&p_h1, g_h1);
    cudaGetSymbolAddress(&p_wt, g_Wt3);
    cudaGetSymbolAddress(&p_st, g_stats3);
    __half* h0 = (__half*)p_h0;
    __half* h1 = (__half*)p_h1;
    const float* Wt = (const float*)p_wt;
    float* st = (float*)p_st;  // st + L*2*DD

    prep_w_all<<<(3 * K2 * DD + 255) / 256, 256>>>(Wl[0], Wr[0], Wl[1], Wr[1], Wl[2], Wr[2]);

    const int NB = (NN + 1023) / 1024;
    count_kernel<<<(E + 255) / 256, 256>>>(ei, E);
    scan_fused_kernel<<<NB, 1024>>>();
    fill_kernel<<<(E + 255) / 256, 256>>>(ei, E);

    const int MB = (NN + 127) / 128;

    layer_kernel<float, 0, __half><<<MB, 128>>>(
        x, Wt, bl[0], nullptr, nullptr, nullptr, st, h0);
    layer_kernel<__half, 1, __half><<<MB, 128>>>(
        h0, Wt + K2 * DD, bl[1], st, gm[0], bt[0], st + 2 * DD, h1);
    layer_kernel<__half, 1, float><<<MB, 128>>>(
        h1, Wt + 2 * K2 * DD, bl[2], st + 2 * DD, gm[1], bt[1], st + 4 * DD, (float*)d_out);
    apply_kernel<<<(NN * DD / 4 + 255) / 256, 256>>>((float*)d_out, st + 4 * DD, gm[2], bt[2]);
}

// round 9
// speedup vs baseline: 1.5050x; 1.5050x over previous
#include <cuda_runtime.h>
#include <cuda_fp16.h>
#include <cstdint>
#include <type_traits>

#define NN 50000
#define DD 128
#define K2 256
#define EE 800000
#define EPS 1e-5f

// ---------------- scratch (device globals) ----------------------------------
__device__ float  g_agg[NN * DD];       // mean-aggregated features (fp32)
__device__ __half g_xh[NN * DD];        // fp16 copy of input x (gather source)
__device__ __half g_h0[NN * DD];
__device__ __half g_h1[NN * DD];
__device__ float  g_Wt3[3 * K2 * DD];
__device__ float  g_stats3[3][2 * DD];  // per-layer raw [sum | sumsq]
__device__ int    g_deg[NN];
__device__ int    g_rowptr[NN + 1];
__device__ int    g_cursor[NN];
__device__ int    g_col[EE];
__device__ int    g_bsum[64];
__device__ int    g_scan_count;

// ---------------- CSR build --------------------------------------------------
__global__ void count_kernel(const int* __restrict__ ei, int E) {
    int e = blockIdx.x * blockDim.x + threadIdx.x;
    if (e < E) {
        int d = ei[E + e];
        if (d >= 0 && d < NN) atomicAdd(&g_deg[d], 1);
    }
}

__global__ void scan_fused_kernel() {
    __shared__ int wsum[32];
    __shared__ int s_off;
    int t = threadIdx.x, b = blockIdx.x;
    int idx = b * 1024 + t;
    int wid = t >> 5, lane = t & 31;
    int v = (idx < NN) ? g_deg[idx] : 0;
    int incl = v;
#pragma unroll
    for (int off = 1; off < 32; off <<= 1) {
        int y = __shfl_up_sync(0xffffffffu, incl, off);
        if (lane >= off) incl += y;
    }
    if (lane == 31) wsum[wid] = incl;
    __syncthreads();
    if (wid == 0) {
        int si = wsum[lane];
#pragma unroll
        for (int off = 1; off < 32; off <<= 1) {
            int y = __shfl_up_sync(0xffffffffu, si, off);
            if (lane >= off) si += y;
        }
        wsum[lane] = si;
    }
    __syncthreads();
    int total = wsum[31];
    if (t == 0) {
        g_bsum[b] = total;
        __threadfence();
        atomicAdd(&g_scan_count, 1);
        while (atomicAdd(&g_scan_count, 0) < (int)gridDim.x) {}
        __threadfence();
        int off = 0;
        for (int j = 0; j < b; j++) off += g_bsum[j];
        s_off = off;
    }
    __syncthreads();
    int woff = (wid > 0) ? wsum[wid - 1] : 0;
    if (idx < NN) {
        int r = s_off + woff + incl - v;
        g_rowptr[idx] = r;
        g_cursor[idx] = r;
    }
    if (b == gridDim.x - 1 && t == 0) g_rowptr[NN] = s_off + total;
}

__global__ void fill_kernel(const int* __restrict__ ei, int E) {
    int e = blockIdx.x * blockDim.x + threadIdx.x;
    if (e < E) {
        int s = ei[e];
        int d = ei[E + e];
        if (d >= 0 && d < NN) {
            int pos = atomicAdd(&g_cursor[d], 1);
            g_col[pos] = s;
        }
    }
}

// ---------------- convert x to fp16 (gather source) --------------------------
__global__ void convert_x_kernel(const float* __restrict__ x) {
    int i = blockIdx.x * blockDim.x + threadIdx.x;  // one per 4 elements
    if (i >= NN * DD / 4) return;
    float4 v = __ldg((const float4*)x + i);
    uint2 o;
    __half2 a = __floats2half2_rn(v.x, v.y);
    __half2 b = __floats2half2_rn(v.z, v.w);
    o.x = *reinterpret_cast<uint32_t*>(&a);
    o.y = *reinterpret_cast<uint32_t*>(&b);
    ((uint2*)g_xh)[i] = o;
}

// ---------------- weight prep + zero deg/stats + scan reset ------------------
__global__ void prep_w_all(const float* __restrict__ Wl0, const float* __restrict__ Wr0,
                           const float* __restrict__ Wl1, const float* __restrict__ Wr1,
                           const float* __restrict__ Wl2, const float* __restrict__ Wr2) {
    int i = blockIdx.x * blockDim.x + threadIdx.x;
    if (i == 0) g_scan_count = 0;
    if (i < NN / 4) ((int4*)g_deg)[i] = make_int4(0, 0, 0, 0);
    if (i < 6 * DD) ((float*)g_stats3)[i] = 0.f;
    if (i >= 3 * K2 * DD) return;
    int L = i / (K2 * DD);
    int r = i - L * (K2 * DD);
    int k = r >> 7, j = r & 127;
    const float* Wl = (L == 0) ? Wl0 : (L == 1 ? Wl1 : Wl2);
    const float* Wr = (L == 0) ? Wr0 : (L == 1 ? Wr1 : Wr2);
    g_Wt3[i] = (k < DD) ? __ldg(&Wl[j * DD + k]) : __ldg(&Wr[j * DD + (k - DD)]);
}

// ---------------- gather (fp16 source, optional fused BN+ReLU) ---------------
// one warp per node; lane handles 4 contiguous features
template <int XFORM>
__global__ void gather_f16(const __half* __restrict__ x,
                           const float* __restrict__ prev_stats,
                           const float* __restrict__ prev_gamma,
                           const float* __restrict__ prev_beta) {
    int w = (blockIdx.x * blockDim.x + threadIdx.x) >> 5;
    int lane = threadIdx.x & 31;
    if (w >= NN) return;
    float4 s4, b4;
    if (XFORM) {
        // compute BN affine of previous layer for this lane's 4 features
        float sc[4], sh[4];
#pragma unroll
        for (int c = 0; c < 4; c++) {
            int f = lane * 4 + c;
            float m = __ldg(&prev_stats[f]) * (1.0f / NN);
            float var = __ldg(&prev_stats[DD + f]) * (1.0f / NN) - m * m;
            float s = __ldg(&prev_gamma[f]) * rsqrtf(var + EPS);
            sc[c] = s;
            sh[c] = __ldg(&prev_beta[f]) - m * s;
        }
        s4 = make_float4(sc[0], sc[1], sc[2], sc[3]);
        b4 = make_float4(sh[0], sh[1], sh[2], sh[3]);
    }
    int start = g_rowptr[w], end = g_rowptr[w + 1];
    float4 acc = make_float4(0.f, 0.f, 0.f, 0.f);

    auto addv = [&](uint2 raw) {
        __half2 ha = *reinterpret_cast<__half2*>(&raw.x);
        __half2 hb = *reinterpret_cast<__half2*>(&raw.y);
        float2 f0 = __half22float2(ha);
        float2 f1 = __half22float2(hb);
        if (XFORM) {
            acc.x += fmaxf(fmaf(f0.x, s4.x, b4.x), 0.f);
            acc.y += fmaxf(fmaf(f0.y, s4.y, b4.y), 0.f);
            acc.z += fmaxf(fmaf(f1.x, s4.z, b4.z), 0.f);
            acc.w += fmaxf(fmaf(f1.y, s4.w, b4.w), 0.f);
        } else {
            acc.x += f0.x; acc.y += f0.y; acc.z += f1.x; acc.w += f1.y;
        }
    };

    int i = start;
    for (; i + 7 < end; i += 8) {
        int sidx[8];
#pragma unroll
        for (int u = 0; u < 8; u++) sidx[u] = __ldg(&g_col[i + u]);
        uint2 rr[8];
#pragma unroll
        for (int u = 0; u < 8; u++)
            rr[u] = __ldg((const uint2*)(x + (size_t)sidx[u] * DD) + lane);
#pragma unroll
        for (int u = 0; u < 8; u++) addv(rr[u]);
    }
    for (; i < end; i++) {
        int s = __ldg(&g_col[i]);
        addv(__ldg((const uint2*)(x + (size_t)s * DD) + lane));
    }
    float sc = 1.0f / fmaxf((float)(end - start), 1.0f);
    acc.x *= sc; acc.y *= sc; acc.z *= sc; acc.w *= sc;
    ((float4*)(g_agg + (size_t)w * DD))[lane] = acc;
}

// ---------------- 3xTF32 tensor-core GEMM + fused BN stats ------------------
#define ASTRIDE 20
#define BSTRIDE 136

__device__ __forceinline__ void split_tf32(float v, uint32_t& hi, uint32_t& lo) {
    asm("cvt.rna.tf32.f32 %0, %1;" : "=r"(hi) : "f"(v));
    float l = v - __uint_as_float(hi);
    asm("cvt.rna.tf32.f32 %0, %1;" : "=r"(lo) : "f"(l));
}

__device__ __forceinline__ void mma_tf32(float* d, uint32_t a0, uint32_t a1,
                                         uint32_t a2, uint32_t a3,
                                         uint32_t b0, uint32_t b1) {
    asm volatile(
        "mma.sync.aligned.m16n8k8.row.col.f32.tf32.tf32.f32 "
        "{%0,%1,%2,%3},{%4,%5,%6,%7},{%8,%9},{%0,%1,%2,%3};"
        : "+f"(d[0]), "+f"(d[1]), "+f"(d[2]), "+f"(d[3])
        : "r"(a0), "r"(a1), "r"(a2), "r"(a3), "r"(b0), "r"(b1));
}

template <typename TI, int XFORM, typename TO>
__global__ __launch_bounds__(128, 2)
void gemm_kernel(const TI* __restrict__ Xin,
                 const float* __restrict__ Wt,
                 const float* __restrict__ bias,
                 const float* __restrict__ prev_stats,
                 const float* __restrict__ prev_gamma,
                 const float* __restrict__ prev_beta,
                 float* __restrict__ cur_stats,
                 TO* __restrict__ Y) {
    __shared__ float As_hi[128 * ASTRIDE];
    __shared__ float As_lo[128 * ASTRIDE];
    __shared__ float Bs_hi[16 * BSTRIDE];
    __shared__ float Bs_lo[16 * BSTRIDE];
    __shared__ float bias_s[128];
    __shared__ float sc_s[128];
    __shared__ float sh_s[128];

    int tid = threadIdx.x;
    int brow = blockIdx.x * 128;
    int wid = tid >> 5, lane = tid & 31;
    int group = lane >> 2, tg = lane & 3;
    int warp_m = (wid >> 1) * 64, warp_n = (wid & 1) * 64;

    if (tid < 128) {
        bias_s[tid] = __ldg(&bias[tid]);
        if (XFORM) {
            float m = __ldg(&prev_stats[tid]) * (1.0f / NN);
            float var = __ldg(&prev_stats[DD + tid]) * (1.0f / NN) - m * m;
            float sc = __ldg(&prev_gamma[tid]) * rsqrtf(var + EPS);
            sc_s[tid] = sc;
            sh_s[tid] = __ldg(&prev_beta[tid]) - m * sc;
        }
    }
    __syncthreads();

    float acc[4][8][4];
#pragma unroll
    for (int mt = 0; mt < 4; mt++)
#pragma unroll
        for (int nt = 0; nt < 8; nt++)
#pragma unroll
            for (int c = 0; c < 4; c++) acc[mt][nt][c] = 0.f;

    float4 pa[4], pb[4];

    auto load_tiles = [&](int kc) {
#pragma unroll
        for (int i = 0; i < 4; i++) {
            int l = tid + i * 128;
            int row = l >> 2, kq = l & 3;
            int r = brow + row;
            float4 v = make_float4(0.f, 0.f, 0.f, 0.f);
            if (r < NN) {
                if (kc < DD) {
                    v = __ldg((const float4*)(g_agg + (size_t)r * DD + kc) + kq);
                } else {
                    int kg = (kc - DD) + kq * 4;
                    if constexpr (std::is_same_v<TI, __half>) {
                        uint2 raw = __ldg((const uint2*)(Xin + (size_t)r * DD + kg));
                        __half2 ha = *reinterpret_cast<__half2*>(&raw.x);
                        __half2 hb = *reinterpret_cast<__half2*>(&raw.y);
                        float2 f0 = __half22float2(ha);
                        float2 f1 = __half22float2(hb);
                        v = make_float4(f0.x, f0.y, f1.x, f1.y);
                    } else {
                        v = __ldg((const float4*)(Xin + (size_t)r * DD + kg));
                    }
                    if (XFORM) {
                        float4 s4 = *(const float4*)(sc_s + kg);
                        float4 b4 = *(const float4*)(sh_s + kg);
                        v.x = fmaxf(fmaf(v.x, s4.x, b4.x), 0.f);
                        v.y = fmaxf(fmaf(v.y, s4.y, b4.y), 0.f);
                        v.z = fmaxf(fmaf(v.z, s4.z, b4.z), 0.f);
                        v.w = fmaxf(fmaf(v.w, s4.w, b4.w), 0.f);
                    }
                }
            }
            pa[i] = v;
        }
#pragma unroll
        for (int i = 0; i < 4; i++) {
            int l = tid + i * 128;
            int k = l >> 5, j4 = l & 31;
            pb[i] = __ldg((const float4*)(Wt + (size_t)(kc + k) * DD) + j4);
        }
    };

    auto store_tiles = [&]() {
#pragma unroll
        for (int i = 0; i < 4; i++) {
            int l = tid + i * 128;
            int row = l >> 2, kq = l & 3;
            float vv[4] = {pa[i].x, pa[i].y, pa[i].z, pa[i].w};
#pragma unroll
            for (int c = 0; c < 4; c++) {
                uint32_t h, lo;
                split_tf32(vv[c], h, lo);
                As_hi[row * ASTRIDE + kq * 4 + c] = __uint_as_float(h);
                As_lo[row * ASTRIDE + kq * 4 + c] = __uint_as_float(lo);
            }
        }
#pragma unroll
        for (int i = 0; i < 4; i++) {
            int l = tid + i * 128;
            int k = l >> 5, j4 = l & 31;
            float vv[4] = {pb[i].x, pb[i].y, pb[i].z, pb[i].w};
#pragma unroll
            for (int c = 0; c < 4; c++) {
                uint32_t h, lo;
                split_tf32(vv[c], h, lo);
                Bs_hi[k * BSTRIDE + j4 * 4 + c] = __uint_as_float(h);
                Bs_lo[k * BSTRIDE + j4 * 4 + c] = __uint_as_float(lo);
            }
        }
    };

    load_tiles(0);

    for (int kc = 0; kc < K2; kc += 16) {
        store_tiles();
        __syncthreads();
        if (kc + 16 < K2) load_tiles(kc + 16);

#pragma unroll
        for (int k0 = 0; k0 < 16; k0 += 8) {
            uint32_t bh0[8], bh1[8], bl0[8], bl1[8];
#pragma unroll
            for (int nt = 0; nt < 8; nt++) {
                int n = warp_n + nt * 8 + group;
                bh0[nt] = __float_as_uint(Bs_hi[(k0 + tg) * BSTRIDE + n]);
                bh1[nt] = __float_as_uint(Bs_hi[(k0 + tg + 4) * BSTRIDE + n]);
                bl0[nt] = __float_as_uint(Bs_lo[(k0 + tg) * BSTRIDE + n]);
                bl1[nt] = __float_as_uint(Bs_lo[(k0 + tg + 4) * BSTRIDE + n]);
            }
#pragma unroll
            for (int mt = 0; mt < 4; mt++) {
                int m = warp_m + mt * 16;
                uint32_t ah0 = __float_as_uint(As_hi[(m + group) * ASTRIDE + k0 + tg]);
                uint32_t ah1 = __float_as_uint(As_hi[(m + group + 8) * ASTRIDE + k0 + tg]);
                uint32_t ah2 = __float_as_uint(As_hi[(m + group) * ASTRIDE + k0 + tg + 4]);
                uint32_t ah3 = __float_as_uint(As_hi[(m + group + 8) * ASTRIDE + k0 + tg + 4]);
                uint32_t al0 = __float_as_uint(As_lo[(m + group) * ASTRIDE + k0 + tg]);
                uint32_t al1 = __float_as_uint(As_lo[(m + group + 8) * ASTRIDE + k0 + tg]);
                uint32_t al2 = __float_as_uint(As_lo[(m + group) * ASTRIDE + k0 + tg + 4]);
                uint32_t al3 = __float_as_uint(As_lo[(m + group + 8) * ASTRIDE + k0 + tg + 4]);
#pragma unroll
                for (int nt = 0; nt < 8; nt++) {
                    mma_tf32(acc[mt][nt], ah0, ah1, ah2, ah3, bh0[nt], bh1[nt]);
                    mma_tf32(acc[mt][nt], al0, al1, al2, al3, bh0[nt], bh1[nt]);
                    mma_tf32(acc[mt][nt], ah0, ah1, ah2, ah3, bl0[nt], bl1[nt]);
                }
            }
        }
        __syncthreads();
    }

    float cs[16], cq[16];
#pragma unroll
    for (int i = 0; i < 16; i++) { cs[i] = 0.f; cq[i] = 0.f; }

#pragma unroll
    for (int mt = 0; mt < 4; mt++) {
        int r0 = brow + warp_m + mt * 16 + group;
        int r1 = r0 + 8;
#pragma unroll
        for (int nt = 0; nt < 8; nt++) {
            int c = warp_n + nt * 8 + 2 * tg;
            float b0 = bias_s[c], b1 = bias_s[c + 1];
            float o0 = acc[mt][nt][0] + b0, o1 = acc[mt][nt][1] + b1;
            float o2 = acc[mt][nt][2] + b0, o3 = acc[mt][nt][3] + b1;
            if (r0 < NN) {
                if constexpr (std::is_same_v<TO, __half>) {
                    *(__half2*)(Y + (size_t)r0 * DD + c) = __floats2half2_rn(o0, o1);
                } else {
                    *(float2*)(Y + (size_t)r0 * DD + c) = make_float2(o0, o1);
                }
                cs[nt * 2 + 0] += o0; cq[nt * 2 + 0] += o0 * o0;
                cs[nt * 2 + 1] += o1; cq[nt * 2 + 1] += o1 * o1;
            }
            if (r1 < NN) {
                if constexpr (std::is_same_v<TO, __half>) {
                    *(__half2*)(Y + (size_t)r1 * DD + c) = __floats2half2_rn(o2, o3);
                } else {
                    *(float2*)(Y + (size_t)r1 * DD + c) = make_float2(o2, o3);
                }
                cs[nt * 2 + 0] += o2; cq[nt * 2 + 0] += o2 * o2;
                cs[nt * 2 + 1] += o3; cq[nt * 2 + 1] += o3 * o3;
            }
        }
    }
#pragma unroll
    for (int i = 0; i < 16; i++) {
#pragma unroll
        for (int off = 4; off < 32; off <<= 1) {
            cs[i] += __shfl_xor_sync(0xffffffffu, cs[i], off);
            cq[i] += __shfl_xor_sync(0xffffffffu, cq[i], off);
        }
    }
    if (group == 0) {
#pragma unroll
        for (int i = 0; i < 16; i++) {
            int c = warp_n + (i >> 1) * 8 + 2 * tg + (i & 1);
            atomicAdd(&cur_stats[c], cs[i]);
            atomicAdd(&cur_stats[DD + c], cq[i]);
        }
    }
}

// ---------------- final BN apply ---------------------------------------------
__global__ void apply_kernel(float* __restrict__ Y,
                             const float* __restrict__ stats,
                             const float* __restrict__ gamma,
                             const float* __restrict__ beta) {
    __shared__ float sc_s[128];
    __shared__ float sh_s[128];
    if (threadIdx.x < 128) {
        int c = threadIdx.x;
        float m = __ldg(&stats[c]) * (1.0f / NN);
        float var = __ldg(&stats[DD + c]) * (1.0f / NN) - m * m;
        float sc = __ldg(&gamma[c]) * rsqrtf(var + EPS);
        sc_s[c] = sc;
        sh_s[c] = __ldg(&beta[c]) - m * sc;
    }
    __syncthreads();
    int i = blockIdx.x * blockDim.x + threadIdx.x;
    if (i >= NN * (DD / 4)) return;
    float4 v = ((float4*)Y)[i];
    int c = (i & (DD / 4 - 1)) * 4;
    float4 s4 = *(const float4*)(sc_s + c);
    float4 b4 = *(const float4*)(sh_s + c);
    v.x = fmaf(v.x, s4.x, b4.x);
    v.y = fmaf(v.y, s4.y, b4.y);
    v.z = fmaf(v.z, s4.z, b4.z);
    v.w = fmaf(v.w, s4.w, b4.w);
    ((float4*)Y)[i] = v;
}

// ---------------- launch ----------------------------------------------------
extern "C" void kernel_launch(void* const* d_in, const int* in_sizes, int n_in,
                              void* d_out, int out_size) {
    const float* x = (const float*)d_in[0];
    const int* ei = (const int*)d_in[1];
    const float* Wl[3] = {(const float*)d_in[2], (const float*)d_in[7], (const float*)d_in[12]};
    const float* bl[3] = {(const float*)d_in[3], (const float*)d_in[8], (const float*)d_in[13]};
    const float* Wr[3] = {(const float*)d_in[4], (const float*)d_in[9], (const float*)d_in[14]};
    const float* gm[3] = {(const float*)d_in[5], (const float*)d_in[10], (const float*)d_in[15]};
    const float* bt[3] = {(const float*)d_in[6], (const float*)d_in[11], (const float*)d_in[16]};
    int E = in_sizes[1] / 2;

    void *p_xh, *p_h0, *p_h1, *p_wt, *p_st;
    cudaGetSymbolAddress(&p_xh, g_xh);
    cudaGetSymbolAddress(&p_h0, g_h0);
    cudaGetSymbolAddress(&p_h1, g_h1);
    cudaGetSymbolAddress(&p_wt, g_Wt3);
    cudaGetSymbolAddress(&p_st, g_stats3);
    __half* xh = (__half*)p_xh;
    __half* h0 = (__half*)p_h0;
    __half* h1 = (__half*)p_h1;
    const float* Wt = (const float*)p_wt;
    float* st = (float*)p_st;

    prep_w_all<<<(3 * K2 * DD + 255) / 256, 256>>>(Wl[0], Wr[0], Wl[1], Wr[1], Wl[2], Wr[2]);
    convert_x_kernel<<<(NN * DD / 4 + 255) / 256, 256>>>(x);

    const int NB = (NN + 1023) / 1024;
    count_kernel<<<(E + 255) / 256, 256>>>(ei, E);
    scan_fused_kernel<<<NB, 1024>>>();
    fill_kernel<<<(E + 255) / 256, 256>>>(ei, E);

    const int GB = (NN * 32 + 255) / 256;
    const int MB = (NN + 127) / 128;

    // layer 0: gather from fp16 x copy; GEMM x-half reads fp32 x
    gather_f16<0><<<GB, 256>>>(xh, nullptr, nullptr, nullptr);
    gemm_kernel<float, 0, __half><<<MB, 128>>>(
        x, Wt, bl[0], nullptr, nullptr, nullptr, st, h0);

    // layer 1
    gather_f16<1><<<GB, 256>>>(h0, st, gm[0], bt[0]);
    gemm_kernel<__half, 1, __half><<<MB, 128>>>(
        h0, Wt + K2 * DD, bl[1], st, gm[0], bt[0], st + 2 * DD, h1);

    // layer 2
    gather_f16<1><<<GB, 256>>>(h1, st + 2 * DD, gm[1], bt[1]);
    gemm_kernel<__half, 1, float><<<MB, 128>>>(
        h1, Wt + 2 * K2 * DD, bl[2], st + 2 * DD, gm[1], bt[1], st + 4 * DD, (float*)d_out);

    apply_kernel<<<(NN * DD / 4 + 255) / 256, 256>>>((float*)d_out, st + 4 * DD, gm[2], bt[2]);
}